// round 1
// baseline (speedup 1.0000x reference)
#include <cuda_runtime.h>
#include <cuda_fp16.h>
#include <cstdint>

// Problem dims (fixed by the dataset)
#define B_  256
#define S_  8
#define F_  2048
#define H_  8
#define N_  (H_*F_)      // 16384
#define M2_ (B_*S_)      // 2048
#define K_  F_           // 2048 per split-GEMM
#define ALPHA_ 0.3f

// GEMM tiling
#define BM 128
#define BN 128
#define BK 32
#define NTHREADS 256
#define NK (K_/BK)       // 64

// Scratch (device globals: no allocations allowed in kernel_launch)
__device__ __half g_Wh[(size_t)M2_ * N_];   // 64MB  Wh[b*8+s][h*2048+f] fp16
__device__ float  g_P0[(size_t)B_  * N_];   // 16MB  P0[b][h*2048+f]
__device__ float  g_e [B_ * H_ * S_];       // e[b][h][s]

// ---------------------------------------------------------------------------
__device__ __forceinline__ void ldsm_x4(uint32_t& r0, uint32_t& r1, uint32_t& r2, uint32_t& r3, const void* p){
    uint32_t addr = (uint32_t)__cvta_generic_to_shared(p);
    asm volatile("ldmatrix.sync.aligned.m8n8.x4.shared.b16 {%0,%1,%2,%3}, [%4];"
                 : "=r"(r0),"=r"(r1),"=r"(r2),"=r"(r3) : "r"(addr));
}
__device__ __forceinline__ void ldsm_x2t(uint32_t& r0, uint32_t& r1, const void* p){
    uint32_t addr = (uint32_t)__cvta_generic_to_shared(p);
    asm volatile("ldmatrix.sync.aligned.m8n8.x2.trans.shared.b16 {%0,%1}, [%2];"
                 : "=r"(r0),"=r"(r1) : "r"(addr));
}
__device__ __forceinline__ void mma16816(float* c, const uint32_t* a, const uint32_t* b){
    asm volatile("mma.sync.aligned.m16n8k16.row.col.f32.f16.f16.f32 "
                 "{%0,%1,%2,%3}, {%4,%5,%6,%7}, {%8,%9}, {%0,%1,%2,%3};"
                 : "+f"(c[0]),"+f"(c[1]),"+f"(c[2]),"+f"(c[3])
                 : "r"(a[0]),"r"(a[1]),"r"(a[2]),"r"(a[3]),"r"(b[0]),"r"(b[1]));
}
__device__ __forceinline__ float lrelu(float z){ return z > 0.f ? z : ALPHA_ * z; }

// ---------------------------------------------------------------------------
// Split GEMM. FIRST=true:  P0[b, h*F+f]   = inputs[b,0,:]  @ W[h, 0:F,  :]
//            FIRST=false: Wh = leaky_relu(inputs[b,s,:] @ W[h, F:2F, :] + P0),
//                          + partial e accumulation via atomics.
// Grid: (Mtiles, 128). blockIdx.x fastest -> CTAs sharing a B-slab are adjacent
// (L2 reuse of W).
// ---------------------------------------------------------------------------
template<bool FIRST>
__global__ void __launch_bounds__(NTHREADS)
gatv2_gemm(const float* __restrict__ inputs,
           const float* __restrict__ W,
           const float* __restrict__ att_w)
{
    __shared__ __half sA[2][BM][BK+8];   // 40-half rows (80B, 16B-aligned)
    __shared__ __half sB[2][BK][BN+8];   // 136-half rows (272B, 16B-aligned)
    __shared__ float  sAw[BN];

    const int mBase = blockIdx.x * BM;
    const int nTile = blockIdx.y;
    const int nBase = nTile * BN;
    const int h     = nTile >> 4;          // 16 N-tiles per head (2048/128)
    const int f0    = (nTile & 15) * BN;

    const int tid   = threadIdx.x;
    const int lane  = tid & 31;
    const int warp  = tid >> 5;
    const int warpM = warp & 1;            // 2 x 4 warp grid, 64x32 per warp
    const int warpN = warp >> 1;

    // A: FIRST -> row m=b, stride S*F (inputs[b,0,:]); else row m=(b,s), stride F
    const size_t aStride = FIRST ? (size_t)(S_*F_) : (size_t)F_;
    // B[k][j] = W[h][cOff+k][f0+j]
    const float* Bbase = W + ((size_t)h * (2*F_) + (FIRST ? 0 : F_)) * (size_t)F_ + f0;

    float4 aReg[4], bReg[4];

    // --- stage 0 load ---
    {
        const int kB = 0;
        #pragma unroll
        for (int i=0;i<4;i++){
            int id = tid + i*NTHREADS;
            int r = id >> 3, c = (id & 7) * 4;                   // A: 8 f4/row
            aReg[i] = *reinterpret_cast<const float4*>(inputs + (size_t)(mBase + r)*aStride + kB + c);
        }
        #pragma unroll
        for (int i=0;i<4;i++){
            int id = tid + i*NTHREADS;
            int r = id >> 5, c = (id & 31) * 4;                  // B: 32 f4/row
            bReg[i] = *reinterpret_cast<const float4*>(Bbase + (size_t)(kB + r)*F_ + c);
        }
        #pragma unroll
        for (int i=0;i<4;i++){
            int id = tid + i*NTHREADS;
            int r = id >> 3, c = (id & 7) * 4;
            *reinterpret_cast<__half2*>(&sA[0][r][c  ]) = __floats2half2_rn(aReg[i].x, aReg[i].y);
            *reinterpret_cast<__half2*>(&sA[0][r][c+2]) = __floats2half2_rn(aReg[i].z, aReg[i].w);
        }
        #pragma unroll
        for (int i=0;i<4;i++){
            int id = tid + i*NTHREADS;
            int r = id >> 5, c = (id & 31) * 4;
            *reinterpret_cast<__half2*>(&sB[0][r][c  ]) = __floats2half2_rn(bReg[i].x, bReg[i].y);
            *reinterpret_cast<__half2*>(&sB[0][r][c+2]) = __floats2half2_rn(bReg[i].z, bReg[i].w);
        }
    }
    __syncthreads();

    float acc[4][4][4];
    #pragma unroll
    for (int a=0;a<4;a++) for (int b=0;b<4;b++) for (int c=0;c<4;c++) acc[a][b][c]=0.f;

    int buf = 0;
    for (int kt = 0; kt < NK; kt++){
        // prefetch next tile into registers
        if (kt < NK-1){
            const int kB = (kt+1)*BK;
            #pragma unroll
            for (int i=0;i<4;i++){
                int id = tid + i*NTHREADS;
                int r = id >> 3, c = (id & 7) * 4;
                aReg[i] = *reinterpret_cast<const float4*>(inputs + (size_t)(mBase + r)*aStride + kB + c);
            }
            #pragma unroll
            for (int i=0;i<4;i++){
                int id = tid + i*NTHREADS;
                int r = id >> 5, c = (id & 31) * 4;
                bReg[i] = *reinterpret_cast<const float4*>(Bbase + (size_t)(kB + r)*F_ + c);
            }
        }
        // compute on current buffer
        #pragma unroll
        for (int kk = 0; kk < BK; kk += 16){
            uint32_t af[4][4];
            #pragma unroll
            for (int mf=0; mf<4; mf++){
                int row = warpM*64 + mf*16 + (lane & 15);
                int col = kk + ((lane >> 4) << 3);
                ldsm_x4(af[mf][0], af[mf][1], af[mf][2], af[mf][3], &sA[buf][row][col]);
            }
            uint32_t bf[4][2];
            #pragma unroll
            for (int nf=0; nf<4; nf++){
                int row = kk + (lane & 15);
                int col = warpN*32 + nf*8;
                ldsm_x2t(bf[nf][0], bf[nf][1], &sB[buf][row][col]);
            }
            #pragma unroll
            for (int mf=0; mf<4; mf++)
                #pragma unroll
                for (int nf=0; nf<4; nf++)
                    mma16816(acc[mf][nf], af[mf], bf[nf]);
        }
        // store prefetched regs to other buffer
        if (kt < NK-1){
            int nb = buf ^ 1;
            #pragma unroll
            for (int i=0;i<4;i++){
                int id = tid + i*NTHREADS;
                int r = id >> 3, c = (id & 7) * 4;
                *reinterpret_cast<__half2*>(&sA[nb][r][c  ]) = __floats2half2_rn(aReg[i].x, aReg[i].y);
                *reinterpret_cast<__half2*>(&sA[nb][r][c+2]) = __floats2half2_rn(aReg[i].z, aReg[i].w);
            }
            #pragma unroll
            for (int i=0;i<4;i++){
                int id = tid + i*NTHREADS;
                int r = id >> 5, c = (id & 31) * 4;
                *reinterpret_cast<__half2*>(&sB[nb][r][c  ]) = __floats2half2_rn(bReg[i].x, bReg[i].y);
                *reinterpret_cast<__half2*>(&sB[nb][r][c+2]) = __floats2half2_rn(bReg[i].z, bReg[i].w);
            }
            __syncthreads();
            buf = nb;
        }
    }

    // ---------------- epilogue ----------------
    const int g  = lane >> 2;   // group (row within 8)
    const int tg = lane & 3;    // col pair selector

    if (FIRST){
        #pragma unroll
        for (int mf=0; mf<4; mf++){
            int r0 = mBase + warpM*64 + mf*16 + g;
            int r1 = r0 + 8;
            #pragma unroll
            for (int nf=0; nf<4; nf++){
                int c0 = nBase + warpN*32 + nf*8 + tg*2;
                *reinterpret_cast<float2*>(&g_P0[(size_t)r0*N_ + c0]) = make_float2(acc[mf][nf][0], acc[mf][nf][1]);
                *reinterpret_cast<float2*>(&g_P0[(size_t)r1*N_ + c0]) = make_float2(acc[mf][nf][2], acc[mf][nf][3]);
            }
        }
    } else {
        __syncthreads();
        if (tid < BN) sAw[tid] = att_w[(size_t)h*F_ + f0 + tid];
        __syncthreads();

        #pragma unroll
        for (int mf=0; mf<4; mf++){
            int r0 = mBase + warpM*64 + mf*16 + g;   // global (b,s) row
            int r1 = r0 + 8;
            float e0 = 0.f, e1 = 0.f;
            #pragma unroll
            for (int nf=0; nf<4; nf++){
                int lc = warpN*32 + nf*8 + tg*2;     // local col for sAw
                int c0 = nBase + lc;                  // global col
                float2 p0 = *reinterpret_cast<const float2*>(&g_P0[(size_t)(r0>>3)*N_ + c0]);
                float2 p1 = *reinterpret_cast<const float2*>(&g_P0[(size_t)(r1>>3)*N_ + c0]);
                float v00 = lrelu(acc[mf][nf][0] + p0.x);
                float v01 = lrelu(acc[mf][nf][1] + p0.y);
                float v10 = lrelu(acc[mf][nf][2] + p1.x);
                float v11 = lrelu(acc[mf][nf][3] + p1.y);
                e0 += v00*sAw[lc] + v01*sAw[lc+1];
                e1 += v10*sAw[lc] + v11*sAw[lc+1];
                *reinterpret_cast<__half2*>(&g_Wh[(size_t)r0*N_ + c0]) = __floats2half2_rn(v00, v01);
                *reinterpret_cast<__half2*>(&g_Wh[(size_t)r1*N_ + c0]) = __floats2half2_rn(v10, v11);
            }
            // reduce over the 4 lanes of the group (tg = low 2 bits of lane)
            e0 += __shfl_xor_sync(0xffffffffu, e0, 1);
            e0 += __shfl_xor_sync(0xffffffffu, e0, 2);
            e1 += __shfl_xor_sync(0xffffffffu, e1, 1);
            e1 += __shfl_xor_sync(0xffffffffu, e1, 2);
            if (tg == 0){
                atomicAdd(&g_e[(r0>>3)*64 + h*8 + (r0&7)], e0);
                atomicAdd(&g_e[(r1>>3)*64 + h*8 + (r1&7)], e1);
            }
        }
    }
}

// ---------------------------------------------------------------------------
__global__ void zero_e_kernel(){
    int i = blockIdx.x * blockDim.x + threadIdx.x;
    if (i < B_*H_*S_) g_e[i] = 0.f;
}

// out[b,s,f] = inputs[b,s,f] + (1/H)*sum_h bias[h,f] + sum_h attn[b,h,s]/H * Wh[b,h,s,f]
__global__ void __launch_bounds__(256)
gatv2_output(const float* __restrict__ inputs,
             const float* __restrict__ bias,
             float* __restrict__ out)
{
    const int b = blockIdx.x;
    __shared__ float attn[H_][S_];
    __shared__ float mbias[F_];
    const int tid = threadIdx.x;

    if (tid < H_){
        float ev[S_];
        float mx = -1e30f;
        #pragma unroll
        for (int s=0;s<S_;s++){ ev[s] = g_e[b*64 + tid*8 + s]; mx = fmaxf(mx, ev[s]); }
        float sum = 0.f;
        #pragma unroll
        for (int s=0;s<S_;s++){ ev[s] = __expf(ev[s]-mx); sum += ev[s]; }
        float inv = 0.125f / sum;   // fold 1/H into attn
        #pragma unroll
        for (int s=0;s<S_;s++) attn[tid][s] = ev[s] * inv;
    }
    for (int f = tid; f < F_; f += 256){
        float sb = 0.f;
        #pragma unroll
        for (int h=0;h<H_;h++) sb += bias[(size_t)h*F_ + f];
        mbias[f] = sb * 0.125f;
    }
    __syncthreads();

    for (int idx = tid; idx < S_*F_; idx += 256){
        int s = idx >> 11;
        int f = idx & (F_-1);
        size_t row = (size_t)(b*S_ + s);
        float accv = inputs[row*F_ + f] + mbias[f];
        size_t base = row*N_ + f;
        #pragma unroll
        for (int h=0; h<H_; h++)
            accv += attn[h][s] * __half2float(g_Wh[base + (size_t)h*F_]);
        out[row*F_ + f] = accv;
    }
}

// ---------------------------------------------------------------------------
// metadata order: inputs [256,8,2048] f32, W [8,4096,2048] f32,
//                 att_w [8,2048] f32, bias [8,2048] f32; output f32 [256,8,2048]
extern "C" void kernel_launch(void* const* d_in, const int* in_sizes, int n_in,
                              void* d_out, int out_size)
{
    const float* inputs = (const float*)d_in[0];
    const float* W      = (const float*)d_in[1];
    const float* att_w  = (const float*)d_in[2];
    const float* bias   = (const float*)d_in[3];
    float* out = (float*)d_out;

    zero_e_kernel<<<(B_*H_*S_ + 255)/256, 256>>>();

    dim3 g1(B_/BM,  N_/BN);   // (2, 128)
    gatv2_gemm<true ><<<g1, NTHREADS>>>(inputs, W, att_w);

    dim3 g2(M2_/BM, N_/BN);   // (16, 128)
    gatv2_gemm<false><<<g2, NTHREADS>>>(inputs, W, att_w);

    gatv2_output<<<B_, 256>>>(inputs, bias, out);
}

// round 3
// speedup vs baseline: 1.0367x; 1.0367x over previous
#include <cuda_runtime.h>
#include <cuda_fp16.h>
#include <cstdint>

// ---------------- problem dims ----------------
#define B_  256
#define S_  8
#define F_  2048
#define H_  8
#define NN  (H_*F_)     // 16384
#define M2  (B_*S_)     // 2048
#define KK  2048        // K per split GEMM
#define ALPHA_ 0.3f

// ---------------- GEMM tiling ----------------
// CTA tile 128(M) x 256(N), BK=32, 4-stage cp.async pipeline, 256 threads,
// warp tile 64x64 (warp grid 2x4).
#define NKT 64                      // 2048/32

// dynamic smem byte layout
#define A_PITCH 80                  // 32 halves + 8 pad  (20 words; conflict-free ldmatrix)
#define B_PITCH 528                 // 256 halves + 8 pad (132 words; conflict-free)
#define A_ST (128*A_PITCH)          // 10240
#define B_ST (32*B_PITCH)           // 16896
#define A_OFF(s) ((s)*A_ST)
#define B_OFF(s) (4*A_ST + (s)*B_ST)
#define AW_OFF   (4*A_ST + 4*B_ST)  // 108544
#define SMEM_TOTAL (AW_OFF + 256*4) // 109568

// ---------------- device scratch ----------------
__device__ __half g_A2[(size_t)M2 * KK];        // 8MB   inputs fp16, row (b*8+s)
__device__ __half g_Wf[(size_t)H_ * 2 * F_ * F_]; // 134MB W fp16, same layout as W
__device__ __half g_Wh[(size_t)M2 * NN];        // 64MB
__device__ float  g_P0[(size_t)B_ * NN];        // 16MB
__device__ float  g_e [B_ * H_ * S_];

// ---------------- helpers ----------------
__device__ __forceinline__ uint32_t smem_u32(const void* p){
    uint32_t a;
    asm("{ .reg .u64 t; cvta.to.shared.u64 t, %1; cvt.u32.u64 %0, t; }" : "=r"(a) : "l"(p));
    return a;
}
__device__ __forceinline__ void ldsm_x4(uint32_t* r, uint32_t addr){
    asm volatile("ldmatrix.sync.aligned.m8n8.x4.shared.b16 {%0,%1,%2,%3}, [%4];"
                 : "=r"(r[0]),"=r"(r[1]),"=r"(r[2]),"=r"(r[3]) : "r"(addr));
}
__device__ __forceinline__ void ldsm_x4t(uint32_t* r, uint32_t addr){
    asm volatile("ldmatrix.sync.aligned.m8n8.x4.trans.shared.b16 {%0,%1,%2,%3}, [%4];"
                 : "=r"(r[0]),"=r"(r[1]),"=r"(r[2]),"=r"(r[3]) : "r"(addr));
}
__device__ __forceinline__ void mma16816(float* c, const uint32_t* a, const uint32_t* b){
    asm volatile("mma.sync.aligned.m16n8k16.row.col.f32.f16.f16.f32 "
                 "{%0,%1,%2,%3}, {%4,%5,%6,%7}, {%8,%9}, {%0,%1,%2,%3};"
                 : "+f"(c[0]),"+f"(c[1]),"+f"(c[2]),"+f"(c[3])
                 : "r"(a[0]),"r"(a[1]),"r"(a[2]),"r"(a[3]),"r"(b[0]),"r"(b[1]));
}
__device__ __forceinline__ void cp16(uint32_t dst, const void* src){
    asm volatile("cp.async.cg.shared.global [%0], [%1], 16;" :: "r"(dst), "l"(src) : "memory");
}
#define CP_COMMIT() asm volatile("cp.async.commit_group;" ::: "memory")
#define CP_WAIT(n)  asm volatile("cp.async.wait_group %0;" :: "n"(n) : "memory")
__device__ __forceinline__ float lrelu(float z){ return z > 0.f ? z : ALPHA_ * z; }

// ---------------------------------------------------------------------------
// FIRST:  P0[b, n]   = inputs[b,0,:](fp16) @ Wf[h, 0:F, :]      (M=256)
// !FIRST: Wh = lrelu( A2 @ Wf[h, F:2F, :] + P0 );  e += Wh . att_w
// ---------------------------------------------------------------------------
template<bool FIRST>
__global__ void __launch_bounds__(256, 1)
gat_gemm(const float* __restrict__ att_w)
{
    extern __shared__ char smem[];
    const uint32_t sb = smem_u32(smem);
    const int tid   = threadIdx.x;
    const int lane  = tid & 31;
    const int wid   = tid >> 5;
    const int warpM = wid & 1;
    const int warpN = wid >> 1;

    const int mBase = blockIdx.x * 128;
    const int nTile = blockIdx.y;
    const int nBase = nTile * 256;
    const int h     = nTile >> 3;
    const int f0    = (nTile & 7) * 256;

    const size_t aStride = FIRST ? (size_t)(8*KK) : (size_t)KK;
    const __half* gB = g_Wf + ((size_t)h*(2*F_) + (FIRST ? 0 : F_)) * F_ + f0;

    float* sAw = (float*)(smem + AW_OFF);
    if (!FIRST) sAw[tid] = att_w[(size_t)h*F_ + f0 + tid];

    auto issue = [&](int s, int kB){
        // A: 128 rows x 4 chunks(16B) = 512 chunks
        #pragma unroll
        for (int i = 0; i < 2; i++){
            const int idx = tid + (i << 8);
            const int row = idx >> 2, ch = idx & 3;
            cp16(sb + A_OFF(s) + row*A_PITCH + ch*16,
                 g_A2 + (size_t)(mBase + row)*aStride + kB + ch*8);
        }
        // B: 32 rows x 32 chunks = 1024 chunks
        #pragma unroll
        for (int i = 0; i < 4; i++){
            const int idx = tid + (i << 8);
            const int row = idx >> 5, ch = idx & 31;
            cp16(sb + B_OFF(s) + row*B_PITCH + ch*16,
                 gB + (size_t)(kB + row)*F_ + ch*8);
        }
    };

    issue(0, 0);  CP_COMMIT();
    issue(1, 32); CP_COMMIT();
    issue(2, 64); CP_COMMIT();

    float acc[4][8][4];
    #pragma unroll
    for (int a = 0; a < 4; a++)
        #pragma unroll
        for (int b = 0; b < 8; b++)
            #pragma unroll
            for (int c = 0; c < 4; c++) acc[a][b][c] = 0.f;

    for (int kt = 0; kt < NKT; kt++){
        CP_WAIT(2);
        __syncthreads();
        if (kt + 3 < NKT) issue((kt + 3) & 3, (kt + 3) * 32);
        CP_COMMIT();

        const uint32_t aB = sb + A_OFF(kt & 3);
        const uint32_t bB = sb + B_OFF(kt & 3);
        #pragma unroll
        for (int kk = 0; kk < 32; kk += 16){
            uint32_t af[4][4];
            #pragma unroll
            for (int mf = 0; mf < 4; mf++)
                ldsm_x4(af[mf], aB + (warpM*64 + mf*16 + (lane & 15))*A_PITCH
                                   + (kk + ((lane >> 4) << 3))*2);
            uint32_t bf[4][4];
            #pragma unroll
            for (int nq = 0; nq < 4; nq++)
                ldsm_x4t(bf[nq], bB + (kk + (lane & 15))*B_PITCH
                                    + (warpN*64 + nq*16 + ((lane >> 4) << 3))*2);
            #pragma unroll
            for (int mf = 0; mf < 4; mf++)
                #pragma unroll
                for (int nq = 0; nq < 4; nq++){
                    mma16816(acc[mf][2*nq],   af[mf], &bf[nq][0]);
                    mma16816(acc[mf][2*nq+1], af[mf], &bf[nq][2]);
                }
        }
    }

    // ---------------- epilogue ----------------
    const int g  = lane >> 2;
    const int tg = lane & 3;

    #pragma unroll
    for (int mf = 0; mf < 4; mf++){
        const int r0 = mBase + warpM*64 + mf*16 + g;
        const int r1 = r0 + 8;
        if (FIRST){
            #pragma unroll
            for (int nf = 0; nf < 8; nf++){
                const int c0 = nBase + warpN*64 + nf*8 + tg*2;
                *reinterpret_cast<float2*>(&g_P0[(size_t)r0*NN + c0]) = make_float2(acc[mf][nf][0], acc[mf][nf][1]);
                *reinterpret_cast<float2*>(&g_P0[(size_t)r1*NN + c0]) = make_float2(acc[mf][nf][2], acc[mf][nf][3]);
            }
        } else {
            float e0 = 0.f, e1 = 0.f;
            #pragma unroll
            for (int nf = 0; nf < 8; nf++){
                const int lc = warpN*64 + nf*8 + tg*2;
                const int c0 = nBase + lc;
                const float2 p0 = *reinterpret_cast<const float2*>(&g_P0[(size_t)(r0 >> 3)*NN + c0]);
                const float2 p1 = *reinterpret_cast<const float2*>(&g_P0[(size_t)(r1 >> 3)*NN + c0]);
                const float v00 = lrelu(acc[mf][nf][0] + p0.x);
                const float v01 = lrelu(acc[mf][nf][1] + p0.y);
                const float v10 = lrelu(acc[mf][nf][2] + p1.x);
                const float v11 = lrelu(acc[mf][nf][3] + p1.y);
                e0 += v00*sAw[lc] + v01*sAw[lc+1];
                e1 += v10*sAw[lc] + v11*sAw[lc+1];
                *reinterpret_cast<__half2*>(&g_Wh[(size_t)r0*NN + c0]) = __floats2half2_rn(v00, v01);
                *reinterpret_cast<__half2*>(&g_Wh[(size_t)r1*NN + c0]) = __floats2half2_rn(v10, v11);
            }
            e0 += __shfl_xor_sync(0xffffffffu, e0, 1);
            e0 += __shfl_xor_sync(0xffffffffu, e0, 2);
            e1 += __shfl_xor_sync(0xffffffffu, e1, 1);
            e1 += __shfl_xor_sync(0xffffffffu, e1, 2);
            if (tg == 0){
                atomicAdd(&g_e[(r0 >> 3)*64 + h*8 + (r0 & 7)], e0);
                atomicAdd(&g_e[(r1 >> 3)*64 + h*8 + (r1 & 7)], e1);
            }
        }
    }
}

// ---------------------------------------------------------------------------
__global__ void zero_e_kernel(){
    int i = blockIdx.x * blockDim.x + threadIdx.x;
    if (i < B_*H_*S_) g_e[i] = 0.f;
}

// inputs fp32 -> g_A2 fp16
__global__ void __launch_bounds__(256) conv_in(const float* __restrict__ in){
    size_t i = (size_t)blockIdx.x * 256 + threadIdx.x;    // float2 index
    const float2 v = ((const float2*)in)[i];
    ((__half2*)g_A2)[i] = __floats2half2_rn(v.x, v.y);
}

// W fp32 -> g_Wf fp16 (same layout, pure streaming convert)
__global__ void __launch_bounds__(256) conv_W(const float* __restrict__ W){
    size_t i = (size_t)blockIdx.x * 256 + threadIdx.x;    // float4 index
    const float4 v = ((const float4*)W)[i];
    __half2 lo = __floats2half2_rn(v.x, v.y);
    __half2 hi = __floats2half2_rn(v.z, v.w);
    uint2 pk;
    pk.x = *reinterpret_cast<uint32_t*>(&lo);
    pk.y = *reinterpret_cast<uint32_t*>(&hi);
    ((uint2*)g_Wf)[i] = pk;
}

// out[b,s,f] = inputs + mean_h(bias) + sum_h attn/H * Wh
__global__ void __launch_bounds__(256) gat_out(const float* __restrict__ in,
                                               const float* __restrict__ bias,
                                               float* __restrict__ out){
    const int bs = blockIdx.x;
    const int b = bs >> 3, s = bs & 7;
    __shared__ float sAttn[H_];
    const int tid = threadIdx.x;
    if (tid < H_){
        float ev[S_]; float mx = -1e30f;
        #pragma unroll
        for (int s2 = 0; s2 < S_; s2++){ ev[s2] = g_e[b*64 + tid*8 + s2]; mx = fmaxf(mx, ev[s2]); }
        float sum = 0.f;
        #pragma unroll
        for (int s2 = 0; s2 < S_; s2++) sum += __expf(ev[s2] - mx);
        sAttn[tid] = __expf(ev[s] - mx) * 0.125f / sum;
    }
    __syncthreads();
    const float2*  in2 = (const float2*)(in + (size_t)bs * F_);
    const float2*  bi2 = (const float2*)bias;
    const __half2* w2  = (const __half2*)(g_Wh + (size_t)bs * NN);
    float2* o2 = (float2*)(out + (size_t)bs * F_);
    #pragma unroll
    for (int i = tid; i < F_/2; i += 256){
        float2 a = in2[i];
        #pragma unroll
        for (int hh = 0; hh < H_; hh++){
            const float2 w  = __half22float2(w2[hh*(F_/2) + i]);
            const float2 bb = bi2[hh*(F_/2) + i];
            a.x += sAttn[hh]*w.x + 0.125f*bb.x;
            a.y += sAttn[hh]*w.y + 0.125f*bb.y;
        }
        o2[i] = a;
    }
}

// ---------------------------------------------------------------------------
extern "C" void kernel_launch(void* const* d_in, const int* in_sizes, int n_in,
                              void* d_out, int out_size)
{
    const float* inputs = (const float*)d_in[0];
    const float* W      = (const float*)d_in[1];
    const float* att_w  = (const float*)d_in[2];
    const float* bias   = (const float*)d_in[3];
    float* out = (float*)d_out;

    cudaFuncSetAttribute(gat_gemm<true>,  cudaFuncAttributeMaxDynamicSharedMemorySize, SMEM_TOTAL);
    cudaFuncSetAttribute(gat_gemm<false>, cudaFuncAttributeMaxDynamicSharedMemorySize, SMEM_TOTAL);

    zero_e_kernel<<<(B_*H_*S_ + 255)/256, 256>>>();
    conv_in<<<(M2*KK/2)/256, 256>>>(inputs);
    conv_W<<<(H_*2*F_*F_/4)/256, 256>>>(W);   // 65536 blocks

    gat_gemm<true ><<<dim3(2, 64),  256, SMEM_TOTAL>>>(att_w);
    gat_gemm<false><<<dim3(16, 64), 256, SMEM_TOTAL>>>(att_w);

    gat_out<<<M2, 256>>>(inputs, bias, out);
}

// round 4
// speedup vs baseline: 1.2001x; 1.1576x over previous
#include <cuda_runtime.h>
#include <cuda_fp16.h>
#include <cstdint>

// ---------------- problem dims ----------------
#define B_  256
#define S_  8
#define F_  2048
#define H_  8
#define NN  (H_*F_)     // 16384
#define M2  (B_*S_)     // 2048
#define KK  2048        // K per split GEMM
#define ALPHA_ 0.3f

// ---------------- GEMM tiling ----------------
// CTA tile 128(M) x 256(N), BK=64, 3-stage cp.async, 512 threads,
// warp grid 2(M) x 8(N) -> warp tile 64x32.
#define NKT 32                      // 2048/64

// smem byte layout
#define A_PITCH 144                 // 64 halves + 8 pad (row phase 16B mod 128 -> conflict-free)
#define B_PITCH 528                 // 256 halves + 8 pad
#define A_ST (128*A_PITCH)          // 18432
#define B_ST (64*B_PITCH)           // 33792
#define STAGE_ST (A_ST + B_ST)      // 52224
#define A_OFF(s) ((s)*STAGE_ST)
#define B_OFF(s) ((s)*STAGE_ST + A_ST)
#define AW_OFF   (3*STAGE_ST)       // 156672
#define SMEM_TOTAL (AW_OFF + 256*4) // 157696

// ---------------- device scratch ----------------
__device__ __half g_A2[(size_t)M2 * KK];          // 8MB
__device__ __half g_Wf[(size_t)H_ * 2 * F_ * F_]; // 134MB
__device__ __half g_Wh[(size_t)M2 * NN];          // 64MB
__device__ __half g_P0[(size_t)B_ * NN];          // 8MB (fp16 now)
__device__ float  g_e [B_ * H_ * S_];

// ---------------- helpers ----------------
__device__ __forceinline__ uint32_t smem_u32(const void* p){
    uint32_t a;
    asm("{ .reg .u64 t; cvta.to.shared.u64 t, %1; cvt.u32.u64 %0, t; }" : "=r"(a) : "l"(p));
    return a;
}
__device__ __forceinline__ void ldsm_x4(uint32_t* r, uint32_t addr){
    asm volatile("ldmatrix.sync.aligned.m8n8.x4.shared.b16 {%0,%1,%2,%3}, [%4];"
                 : "=r"(r[0]),"=r"(r[1]),"=r"(r[2]),"=r"(r[3]) : "r"(addr));
}
__device__ __forceinline__ void ldsm_x4t(uint32_t* r, uint32_t addr){
    asm volatile("ldmatrix.sync.aligned.m8n8.x4.trans.shared.b16 {%0,%1,%2,%3}, [%4];"
                 : "=r"(r[0]),"=r"(r[1]),"=r"(r[2]),"=r"(r[3]) : "r"(addr));
}
__device__ __forceinline__ void mma16816(float* c, const uint32_t* a, const uint32_t* b){
    asm volatile("mma.sync.aligned.m16n8k16.row.col.f32.f16.f16.f32 "
                 "{%0,%1,%2,%3}, {%4,%5,%6,%7}, {%8,%9}, {%0,%1,%2,%3};"
                 : "+f"(c[0]),"+f"(c[1]),"+f"(c[2]),"+f"(c[3])
                 : "r"(a[0]),"r"(a[1]),"r"(a[2]),"r"(a[3]),"r"(b[0]),"r"(b[1]));
}
__device__ __forceinline__ void cp16(uint32_t dst, const void* src){
    asm volatile("cp.async.cg.shared.global [%0], [%1], 16;" :: "r"(dst), "l"(src) : "memory");
}
#define CP_COMMIT() asm volatile("cp.async.commit_group;" ::: "memory")
#define CP_WAIT(n)  asm volatile("cp.async.wait_group %0;" :: "n"(n) : "memory")
__device__ __forceinline__ float lrelu(float z){ return z > 0.f ? z : ALPHA_ * z; }

// ---------------------------------------------------------------------------
// FIRST:  P0[b, n](fp16) = inputs[b,0,:](fp16) @ Wf[h, 0:F, :]     (M=256)
// !FIRST: Wh = lrelu( A2 @ Wf[h, F:2F, :] + P0 );  e += Wh . att_w
// ---------------------------------------------------------------------------
template<bool FIRST>
__global__ void __launch_bounds__(512, 1)
gat_gemm(const float* __restrict__ att_w)
{
    extern __shared__ char smem[];
    const uint32_t sb = smem_u32(smem);
    const int tid   = threadIdx.x;
    const int lane  = tid & 31;
    const int wid   = tid >> 5;
    const int warpM = wid & 1;       // 2 M-warps
    const int warpN = wid >> 1;      // 8 N-warps (32 cols each)

    const int mBase = blockIdx.x * 128;
    const int nTile = blockIdx.y;
    const int nBase = nTile * 256;
    const int h     = nTile >> 3;
    const int f0    = (nTile & 7) * 256;

    const size_t aStride = FIRST ? (size_t)(8*KK) : (size_t)KK;
    const __half* gB = g_Wf + ((size_t)h*(2*F_) + (FIRST ? 0 : F_)) * F_ + f0;

    float* sAw = (float*)(smem + AW_OFF);
    if (!FIRST && tid < 256) sAw[tid] = att_w[(size_t)h*F_ + f0 + tid];

    auto issue = [&](int s, int kB){
        // A: 128 rows x 8 chunks(16B) = 1024 chunks, 512 thr -> 2 each
        #pragma unroll
        for (int i = 0; i < 2; i++){
            const int idx = tid + (i << 9);
            const int row = idx >> 3, ch = idx & 7;
            cp16(sb + A_OFF(s) + row*A_PITCH + ch*16,
                 g_A2 + (size_t)(mBase + row)*aStride + kB + ch*8);
        }
        // B: 64 rows x 32 chunks = 2048 chunks -> 4 each
        #pragma unroll
        for (int i = 0; i < 4; i++){
            const int idx = tid + (i << 9);
            const int row = idx >> 5, ch = idx & 31;
            cp16(sb + B_OFF(s) + row*B_PITCH + ch*16,
                 gB + (size_t)(kB + row)*F_ + ch*8);
        }
    };

    issue(0, 0);  CP_COMMIT();
    issue(1, 64); CP_COMMIT();

    float acc[4][4][4];
    #pragma unroll
    for (int a = 0; a < 4; a++)
        #pragma unroll
        for (int b = 0; b < 4; b++)
            #pragma unroll
            for (int c = 0; c < 4; c++) acc[a][b][c] = 0.f;

    for (int kt = 0; kt < NKT; kt++){
        CP_WAIT(1);
        __syncthreads();
        if (kt + 2 < NKT) issue((kt + 2) % 3, (kt + 2) * 64);
        CP_COMMIT();

        const uint32_t aB = sb + A_OFF(kt % 3);
        const uint32_t bB = sb + B_OFF(kt % 3);
        #pragma unroll
        for (int kk = 0; kk < 64; kk += 16){
            uint32_t af[4][4];
            #pragma unroll
            for (int mf = 0; mf < 4; mf++)
                ldsm_x4(af[mf], aB + (warpM*64 + mf*16 + (lane & 15))*A_PITCH
                                   + (kk + ((lane >> 4) << 3))*2);
            uint32_t bf[2][4];
            #pragma unroll
            for (int nq = 0; nq < 2; nq++)
                ldsm_x4t(bf[nq], bB + (kk + (lane & 15))*B_PITCH
                                    + (warpN*32 + nq*16 + ((lane >> 4) << 3))*2);
            #pragma unroll
            for (int mf = 0; mf < 4; mf++)
                #pragma unroll
                for (int nq = 0; nq < 2; nq++){
                    mma16816(acc[mf][2*nq],   af[mf], &bf[nq][0]);
                    mma16816(acc[mf][2*nq+1], af[mf], &bf[nq][2]);
                }
        }
    }

    // ---------------- epilogue ----------------
    const int g  = lane >> 2;
    const int tg = lane & 3;

    #pragma unroll
    for (int mf = 0; mf < 4; mf++){
        const int r0 = mBase + warpM*64 + mf*16 + g;
        const int r1 = r0 + 8;
        if (FIRST){
            #pragma unroll
            for (int nf = 0; nf < 4; nf++){
                const int c0 = nBase + warpN*32 + nf*8 + tg*2;
                *reinterpret_cast<__half2*>(&g_P0[(size_t)r0*NN + c0]) = __floats2half2_rn(acc[mf][nf][0], acc[mf][nf][1]);
                *reinterpret_cast<__half2*>(&g_P0[(size_t)r1*NN + c0]) = __floats2half2_rn(acc[mf][nf][2], acc[mf][nf][3]);
            }
        } else {
            float e0 = 0.f, e1 = 0.f;
            #pragma unroll
            for (int nf = 0; nf < 4; nf++){
                const int lc = warpN*32 + nf*8 + tg*2;
                const int c0 = nBase + lc;
                const float2 p0 = __half22float2(*reinterpret_cast<const __half2*>(&g_P0[(size_t)(r0 >> 3)*NN + c0]));
                const float2 p1 = __half22float2(*reinterpret_cast<const __half2*>(&g_P0[(size_t)(r1 >> 3)*NN + c0]));
                const float v00 = lrelu(acc[mf][nf][0] + p0.x);
                const float v01 = lrelu(acc[mf][nf][1] + p0.y);
                const float v10 = lrelu(acc[mf][nf][2] + p1.x);
                const float v11 = lrelu(acc[mf][nf][3] + p1.y);
                e0 += v00*sAw[lc] + v01*sAw[lc+1];
                e1 += v10*sAw[lc] + v11*sAw[lc+1];
                *reinterpret_cast<__half2*>(&g_Wh[(size_t)r0*NN + c0]) = __floats2half2_rn(v00, v01);
                *reinterpret_cast<__half2*>(&g_Wh[(size_t)r1*NN + c0]) = __floats2half2_rn(v10, v11);
            }
            e0 += __shfl_xor_sync(0xffffffffu, e0, 1);
            e0 += __shfl_xor_sync(0xffffffffu, e0, 2);
            e1 += __shfl_xor_sync(0xffffffffu, e1, 1);
            e1 += __shfl_xor_sync(0xffffffffu, e1, 2);
            if (tg == 0){
                atomicAdd(&g_e[(r0 >> 3)*64 + h*8 + (r0 & 7)], e0);
                atomicAdd(&g_e[(r1 >> 3)*64 + h*8 + (r1 & 7)], e1);
            }
        }
    }
}

// ---------------------------------------------------------------------------
__global__ void zero_e_kernel(){
    int i = blockIdx.x * blockDim.x + threadIdx.x;
    if (i < B_*H_*S_) g_e[i] = 0.f;
}

// inputs fp32 -> g_A2 fp16
__global__ void __launch_bounds__(256) conv_in(const float* __restrict__ in){
    size_t i = (size_t)blockIdx.x * 256 + threadIdx.x;    // float2 index
    const float2 v = ((const float2*)in)[i];
    ((__half2*)g_A2)[i] = __floats2half2_rn(v.x, v.y);
}

// W fp32 -> g_Wf fp16 (same layout)
__global__ void __launch_bounds__(256) conv_W(const float* __restrict__ W){
    size_t i = (size_t)blockIdx.x * 256 + threadIdx.x;    // float4 index
    const float4 v = ((const float4*)W)[i];
    __half2 lo = __floats2half2_rn(v.x, v.y);
    __half2 hi = __floats2half2_rn(v.z, v.w);
    uint2 pk;
    pk.x = *reinterpret_cast<uint32_t*>(&lo);
    pk.y = *reinterpret_cast<uint32_t*>(&hi);
    ((uint2*)g_Wf)[i] = pk;
}

// out[b,s,f] = inputs + mean_h(bias) + sum_h attn/H * Wh
__global__ void __launch_bounds__(256) gat_out(const float* __restrict__ in,
                                               const float* __restrict__ bias,
                                               float* __restrict__ out){
    const int bs = blockIdx.x;
    const int b = bs >> 3, s = bs & 7;
    __shared__ float sAttn[H_];
    const int tid = threadIdx.x;
    if (tid < H_){
        float ev[S_]; float mx = -1e30f;
        #pragma unroll
        for (int s2 = 0; s2 < S_; s2++){ ev[s2] = g_e[b*64 + tid*8 + s2]; mx = fmaxf(mx, ev[s2]); }
        float sum = 0.f;
        #pragma unroll
        for (int s2 = 0; s2 < S_; s2++) sum += __expf(ev[s2] - mx);
        sAttn[tid] = __expf(ev[s] - mx) * 0.125f / sum;
    }
    __syncthreads();
    const float2*  in2 = (const float2*)(in + (size_t)bs * F_);
    const float2*  bi2 = (const float2*)bias;
    const __half2* w2  = (const __half2*)(g_Wh + (size_t)bs * NN);
    float2* o2 = (float2*)(out + (size_t)bs * F_);
    #pragma unroll
    for (int i = tid; i < F_/2; i += 256){
        float2 a = in2[i];
        #pragma unroll
        for (int hh = 0; hh < H_; hh++){
            const float2 w  = __half22float2(w2[hh*(F_/2) + i]);
            const float2 bb = bi2[hh*(F_/2) + i];
            a.x += sAttn[hh]*w.x + 0.125f*bb.x;
            a.y += sAttn[hh]*w.y + 0.125f*bb.y;
        }
        o2[i] = a;
    }
}

// ---------------------------------------------------------------------------
extern "C" void kernel_launch(void* const* d_in, const int* in_sizes, int n_in,
                              void* d_out, int out_size)
{
    const float* inputs = (const float*)d_in[0];
    const float* W      = (const float*)d_in[1];
    const float* att_w  = (const float*)d_in[2];
    const float* bias   = (const float*)d_in[3];
    float* out = (float*)d_out;

    cudaFuncSetAttribute(gat_gemm<true>,  cudaFuncAttributeMaxDynamicSharedMemorySize, SMEM_TOTAL);
    cudaFuncSetAttribute(gat_gemm<false>, cudaFuncAttributeMaxDynamicSharedMemorySize, SMEM_TOTAL);

    zero_e_kernel<<<(B_*H_*S_ + 255)/256, 256>>>();
    conv_in<<<(M2*KK/2)/256, 256>>>(inputs);
    conv_W<<<(H_*2*F_*F_/4)/256, 256>>>(W);

    gat_gemm<true ><<<dim3(2, 64),  512, SMEM_TOTAL>>>(att_w);
    gat_gemm<false><<<dim3(16, 64), 512, SMEM_TOTAL>>>(att_w);

    gat_out<<<M2, 256>>>(inputs, bias, out);
}

// round 5
// speedup vs baseline: 1.2904x; 1.0752x over previous
#include <cuda_runtime.h>
#include <cuda_fp16.h>
#include <cstdint>

// ---------------- problem dims ----------------
#define B_  256
#define S_  8
#define F_  2048
#define H_  8
#define NN  (H_*F_)     // 16384
#define M2  (B_*S_)     // 2048
#define KK  2048        // K per split GEMM
#define ALPHA_ 0.3f

// ---------------- GEMM tiling ----------------
// CTA tile 128(M) x 256(N), BK=64, 3-stage cp.async, 256 threads,
// warp grid 2(M) x 4(N) -> warp tile 64x64, register double-buffered fragments.
#define NKT 32                      // 2048/64

// smem byte layout
#define A_PITCH 144                 // 64 halves + 8 pad (phase 16B mod 128 -> conflict-free ldsm)
#define B_PITCH 528                 // 256 halves + 8 pad
#define A_ST (128*A_PITCH)          // 18432
#define B_ST (64*B_PITCH)           // 33792
#define STAGE_ST (A_ST + B_ST)      // 52224
#define A_OFF(s) ((s)*STAGE_ST)
#define B_OFF(s) ((s)*STAGE_ST + A_ST)
#define AW_OFF   (3*STAGE_ST)       // 156672
#define SMEM_TOTAL (AW_OFF + 256*4) // 157696

// ---------------- device scratch ----------------
__device__ __half g_A2[(size_t)M2 * KK];          // 8MB
__device__ __half g_Wf[(size_t)H_ * 2 * F_ * F_]; // 134MB
__device__ __half g_Wh[(size_t)M2 * NN];          // 64MB
__device__ __half g_P0[(size_t)B_ * NN];          // 8MB
__device__ float  g_e [B_ * H_ * S_];

// ---------------- helpers ----------------
__device__ __forceinline__ uint32_t smem_u32(const void* p){
    uint32_t a;
    asm("{ .reg .u64 t; cvta.to.shared.u64 t, %1; cvt.u32.u64 %0, t; }" : "=r"(a) : "l"(p));
    return a;
}
__device__ __forceinline__ void ldsm_x4(uint32_t* r, uint32_t addr){
    asm volatile("ldmatrix.sync.aligned.m8n8.x4.shared.b16 {%0,%1,%2,%3}, [%4];"
                 : "=r"(r[0]),"=r"(r[1]),"=r"(r[2]),"=r"(r[3]) : "r"(addr));
}
__device__ __forceinline__ void ldsm_x4t(uint32_t* r, uint32_t addr){
    asm volatile("ldmatrix.sync.aligned.m8n8.x4.trans.shared.b16 {%0,%1,%2,%3}, [%4];"
                 : "=r"(r[0]),"=r"(r[1]),"=r"(r[2]),"=r"(r[3]) : "r"(addr));
}
__device__ __forceinline__ void mma16816(float* c, const uint32_t* a, const uint32_t* b){
    asm volatile("mma.sync.aligned.m16n8k16.row.col.f32.f16.f16.f32 "
                 "{%0,%1,%2,%3}, {%4,%5,%6,%7}, {%8,%9}, {%0,%1,%2,%3};"
                 : "+f"(c[0]),"+f"(c[1]),"+f"(c[2]),"+f"(c[3])
                 : "r"(a[0]),"r"(a[1]),"r"(a[2]),"r"(a[3]),"r"(b[0]),"r"(b[1]));
}
__device__ __forceinline__ void cp16(uint32_t dst, const void* src){
    asm volatile("cp.async.cg.shared.global [%0], [%1], 16;" :: "r"(dst), "l"(src) : "memory");
}
#define CP_COMMIT() asm volatile("cp.async.commit_group;" ::: "memory")
#define CP_WAIT(n)  asm volatile("cp.async.wait_group %0;" :: "n"(n) : "memory")
__device__ __forceinline__ float lrelu(float z){ return z > 0.f ? z : ALPHA_ * z; }

// ---------------------------------------------------------------------------
// FIRST:  P0[b, n](fp16) = inputs[b,0,:](fp16) @ Wf[h, 0:F, :]     (M=256)
// !FIRST: Wh = lrelu( A2 @ Wf[h, F:2F, :] + P0 );  e += Wh . att_w
// ---------------------------------------------------------------------------
template<bool FIRST>
__global__ void __launch_bounds__(256, 1)
gat_gemm(const float* __restrict__ att_w)
{
    extern __shared__ char smem[];
    const uint32_t sb = smem_u32(smem);
    const int tid   = threadIdx.x;
    const int lane  = tid & 31;
    const int wid   = tid >> 5;
    const int warpM = wid & 1;       // 2 M-warps (64 rows each)
    const int warpN = wid >> 1;      // 4 N-warps (64 cols each)

    const int mBase = blockIdx.x * 128;
    const int nTile = blockIdx.y;
    const int nBase = nTile * 256;
    const int h     = nTile >> 3;
    const int f0    = (nTile & 7) * 256;

    const size_t aStride = FIRST ? (size_t)(8*KK) : (size_t)KK;
    const __half* gB = g_Wf + ((size_t)h*(2*F_) + (FIRST ? 0 : F_)) * F_ + f0;

    float* sAw = (float*)(smem + AW_OFF);
    if (!FIRST) sAw[tid] = att_w[(size_t)h*F_ + f0 + tid];

    auto issue = [&](int s, int kB){
        // A: 128 rows x 8 chunks(16B) = 1024 chunks, 256 thr -> 4 each
        #pragma unroll
        for (int i = 0; i < 4; i++){
            const int idx = tid + (i << 8);
            const int row = idx >> 3, ch = idx & 7;
            cp16(sb + A_OFF(s) + row*A_PITCH + ch*16,
                 g_A2 + (size_t)(mBase + row)*aStride + kB + ch*8);
        }
        // B: 64 rows x 32 chunks = 2048 chunks -> 8 each
        #pragma unroll
        for (int i = 0; i < 8; i++){
            const int idx = tid + (i << 8);
            const int row = idx >> 5, ch = idx & 31;
            cp16(sb + B_OFF(s) + row*B_PITCH + ch*16,
                 gB + (size_t)(kB + row)*F_ + ch*8);
        }
    };

    // per-warp smem base offsets for fragment loads
    const uint32_t aRow = (uint32_t)(warpM*64 + (lane & 15)) * A_PITCH + (((uint32_t)lane >> 4) << 4); // +8 halves = 16B
    const uint32_t bCol = (uint32_t)(warpN*64 + ((lane >> 4) << 3)) * 2;
    const uint32_t bRow = (uint32_t)(lane & 15) * B_PITCH;

    uint32_t af[2][4][4], bf[2][4][4];

    auto load_frags = [&](int buf, uint32_t aB, uint32_t bB, int kkh /*k offset in halves*/){
        #pragma unroll
        for (int mf = 0; mf < 4; mf++)
            ldsm_x4(af[buf][mf], aB + aRow + (uint32_t)(mf*16)*A_PITCH + kkh*2);
        #pragma unroll
        for (int nq = 0; nq < 4; nq++)
            ldsm_x4t(bf[buf][nq], bB + bRow + kkh*2*B_PITCH/ (2) * 2 /*see below*/ + bCol + (uint32_t)(nq*16)*2);
    };
    // NOTE: the expression above must be  bB + (kkh)*B_PITCH ... rewrite cleanly:

    float acc[4][8][4];
    #pragma unroll
    for (int a = 0; a < 4; a++)
        #pragma unroll
        for (int b = 0; b < 8; b++)
            #pragma unroll
            for (int c = 0; c < 4; c++) acc[a][b][c] = 0.f;

    // ---- prologue ----
    issue(0, 0);  CP_COMMIT();
    issue(1, 64); CP_COMMIT();
    CP_WAIT(1);
    __syncthreads();

    // clean fragment loaders (replacing the placeholder lambda above)
    auto load_a = [&](int buf, uint32_t aB, int kk16){
        #pragma unroll
        for (int mf = 0; mf < 4; mf++)
            ldsm_x4(af[buf][mf], aB + aRow + (uint32_t)(mf*16)*A_PITCH + (uint32_t)(kk16*16)*2);
    };
    auto load_b = [&](int buf, uint32_t bB, int kk16){
        #pragma unroll
        for (int nq = 0; nq < 4; nq++)
            ldsm_x4t(bf[buf][nq], bB + (uint32_t)(kk16*16)*B_PITCH + bRow + bCol + (uint32_t)(nq*16)*2);
    };

    load_a(0, sb + A_OFF(0), 0);
    load_b(0, sb + B_OFF(0), 0);

    for (int kt = 0; kt < NKT; kt++){
        const int s  = kt % 3;
        const int sn = (kt + 1) % 3;
        const uint32_t aB  = sb + A_OFF(s),  bB  = sb + B_OFF(s);
        const uint32_t aBn = sb + A_OFF(sn), bBn = sb + B_OFF(sn);

        #pragma unroll
        for (int kk = 0; kk < 4; kk++){
            const int cur = kk & 1, nxt = cur ^ 1;
            if (kk == 0 && kt + 2 < NKT){
                issue((kt + 2) % 3, (kt + 2) * 64);
                CP_COMMIT();
            }
            if (kk < 3){
                load_a(nxt, aB, kk + 1);
                load_b(nxt, bB, kk + 1);
            } else if (kt + 1 < NKT){
                CP_WAIT(1);
                __syncthreads();
                load_a(nxt, aBn, 0);
                load_b(nxt, bBn, 0);
            }
            #pragma unroll
            for (int mf = 0; mf < 4; mf++)
                #pragma unroll
                for (int nq = 0; nq < 4; nq++){
                    mma16816(acc[mf][2*nq],   af[cur][mf], &bf[cur][nq][0]);
                    mma16816(acc[mf][2*nq+1], af[cur][mf], &bf[cur][nq][2]);
                }
        }
    }

    // ---------------- epilogue ----------------
    const int g  = lane >> 2;
    const int tg = lane & 3;

    #pragma unroll
    for (int mf = 0; mf < 4; mf++){
        const int r0 = mBase + warpM*64 + mf*16 + g;
        const int r1 = r0 + 8;
        if (FIRST){
            #pragma unroll
            for (int nf = 0; nf < 8; nf++){
                const int c0 = nBase + warpN*64 + nf*8 + tg*2;
                *reinterpret_cast<__half2*>(&g_P0[(size_t)r0*NN + c0]) = __floats2half2_rn(acc[mf][nf][0], acc[mf][nf][1]);
                *reinterpret_cast<__half2*>(&g_P0[(size_t)r1*NN + c0]) = __floats2half2_rn(acc[mf][nf][2], acc[mf][nf][3]);
            }
        } else {
            float e0 = 0.f, e1 = 0.f;
            #pragma unroll
            for (int nf = 0; nf < 8; nf++){
                const int lc = warpN*64 + nf*8 + tg*2;
                const int c0 = nBase + lc;
                const float2 p0 = __half22float2(*reinterpret_cast<const __half2*>(&g_P0[(size_t)(r0 >> 3)*NN + c0]));
                const float2 p1 = __half22float2(*reinterpret_cast<const __half2*>(&g_P0[(size_t)(r1 >> 3)*NN + c0]));
                const float v00 = lrelu(acc[mf][nf][0] + p0.x);
                const float v01 = lrelu(acc[mf][nf][1] + p0.y);
                const float v10 = lrelu(acc[mf][nf][2] + p1.x);
                const float v11 = lrelu(acc[mf][nf][3] + p1.y);
                e0 += v00*sAw[lc] + v01*sAw[lc+1];
                e1 += v10*sAw[lc] + v11*sAw[lc+1];
                *reinterpret_cast<__half2*>(&g_Wh[(size_t)r0*NN + c0]) = __floats2half2_rn(v00, v01);
                *reinterpret_cast<__half2*>(&g_Wh[(size_t)r1*NN + c0]) = __floats2half2_rn(v10, v11);
            }
            e0 += __shfl_xor_sync(0xffffffffu, e0, 1);
            e0 += __shfl_xor_sync(0xffffffffu, e0, 2);
            e1 += __shfl_xor_sync(0xffffffffu, e1, 1);
            e1 += __shfl_xor_sync(0xffffffffu, e1, 2);
            if (tg == 0){
                atomicAdd(&g_e[(r0 >> 3)*64 + h*8 + (r0 & 7)], e0);
                atomicAdd(&g_e[(r1 >> 3)*64 + h*8 + (r1 & 7)], e1);
            }
        }
    }
}

// ---------------------------------------------------------------------------
__global__ void zero_e_kernel(){
    int i = blockIdx.x * blockDim.x + threadIdx.x;
    if (i < B_*H_*S_) g_e[i] = 0.f;
}

// inputs fp32 -> g_A2 fp16
__global__ void __launch_bounds__(256) conv_in(const float* __restrict__ in){
    size_t i = (size_t)blockIdx.x * 256 + threadIdx.x;
    const float2 v = ((const float2*)in)[i];
    ((__half2*)g_A2)[i] = __floats2half2_rn(v.x, v.y);
}

// W fp32 -> g_Wf fp16 (same layout)
__global__ void __launch_bounds__(256) conv_W(const float* __restrict__ W){
    size_t i = (size_t)blockIdx.x * 256 + threadIdx.x;
    const float4 v = ((const float4*)W)[i];
    __half2 lo = __floats2half2_rn(v.x, v.y);
    __half2 hi = __floats2half2_rn(v.z, v.w);
    uint2 pk;
    pk.x = *reinterpret_cast<uint32_t*>(&lo);
    pk.y = *reinterpret_cast<uint32_t*>(&hi);
    ((uint2*)g_Wf)[i] = pk;
}

// out[b,s,f] = inputs + mean_h(bias) + sum_h attn/H * Wh
__global__ void __launch_bounds__(256) gat_out(const float* __restrict__ in,
                                               const float* __restrict__ bias,
                                               float* __restrict__ out){
    const int bs = blockIdx.x;
    const int b = bs >> 3, s = bs & 7;
    __shared__ float sAttn[H_];
    const int tid = threadIdx.x;
    if (tid < H_){
        float ev[S_]; float mx = -1e30f;
        #pragma unroll
        for (int s2 = 0; s2 < S_; s2++){ ev[s2] = g_e[b*64 + tid*8 + s2]; mx = fmaxf(mx, ev[s2]); }
        float sum = 0.f;
        #pragma unroll
        for (int s2 = 0; s2 < S_; s2++) sum += __expf(ev[s2] - mx);
        sAttn[tid] = __expf(ev[s] - mx) * 0.125f / sum;
    }
    __syncthreads();
    const float2*  in2 = (const float2*)(in + (size_t)bs * F_);
    const float2*  bi2 = (const float2*)bias;
    const __half2* w2  = (const __half2*)(g_Wh + (size_t)bs * NN);
    float2* o2 = (float2*)(out + (size_t)bs * F_);
    #pragma unroll
    for (int i = tid; i < F_/2; i += 256){
        float2 a = in2[i];
        #pragma unroll
        for (int hh = 0; hh < H_; hh++){
            const float2 w  = __half22float2(w2[hh*(F_/2) + i]);
            const float2 bb = bi2[hh*(F_/2) + i];
            a.x += sAttn[hh]*w.x + 0.125f*bb.x;
            a.y += sAttn[hh]*w.y + 0.125f*bb.y;
        }
        o2[i] = a;
    }
}

// ---------------------------------------------------------------------------
extern "C" void kernel_launch(void* const* d_in, const int* in_sizes, int n_in,
                              void* d_out, int out_size)
{
    const float* inputs = (const float*)d_in[0];
    const float* W      = (const float*)d_in[1];
    const float* att_w  = (const float*)d_in[2];
    const float* bias   = (const float*)d_in[3];
    float* out = (float*)d_out;

    cudaFuncSetAttribute(gat_gemm<true>,  cudaFuncAttributeMaxDynamicSharedMemorySize, SMEM_TOTAL);
    cudaFuncSetAttribute(gat_gemm<false>, cudaFuncAttributeMaxDynamicSharedMemorySize, SMEM_TOTAL);

    zero_e_kernel<<<(B_*H_*S_ + 255)/256, 256>>>();
    conv_in<<<(M2*KK/2)/256, 256>>>(inputs);
    conv_W<<<(H_*2*F_*F_/4)/256, 256>>>(W);

    gat_gemm<true ><<<dim3(2, 64),  256, SMEM_TOTAL>>>(att_w);
    gat_gemm<false><<<dim3(16, 64), 256, SMEM_TOTAL>>>(att_w);

    gat_out<<<M2, 256>>>(inputs, bias, out);
}

// round 6
// speedup vs baseline: 1.3325x; 1.0327x over previous
#include <cuda_runtime.h>
#include <cuda_fp16.h>
#include <cstdint>

// ---------------- problem dims ----------------
#define B_  256
#define S_  8
#define F_  2048
#define H_  8
#define NN  (H_*F_)     // 16384
#define M2  (B_*S_)     // 2048
#define KK  2048        // K per split GEMM
#define ALPHA_ 0.3f

// ---------------- GEMM tiling ----------------
// CTA tile 128(M) x 256(N), BK=64, 4-stage cp.async, 512 threads,
// warp grid 2(M) x 8(N) -> warp tile 64x32, register double-buffered frags.
#define NKT 32                      // 2048/64

// smem byte layout
#define A_PITCH 144                 // 64 halves + 8 pad (phase 16B mod 128 -> conflict-free)
#define B_PITCH 528                 // 256 halves + 8 pad
#define A_ST (128*A_PITCH)          // 18432
#define B_ST (64*B_PITCH)           // 33792
#define STAGE_ST (A_ST + B_ST)      // 52224
#define A_OFF(s) ((s)*STAGE_ST)
#define B_OFF(s) ((s)*STAGE_ST + A_ST)
#define AW_OFF   (4*STAGE_ST)       // 208896
#define SMEM_TOTAL (AW_OFF + 256*4) // 209920

// ---------------- device scratch ----------------
__device__ __half g_A2[(size_t)M2 * KK];          // 8MB
__device__ __half g_Wf[(size_t)H_ * 2 * F_ * F_]; // 134MB
__device__ __half g_Wh[(size_t)M2 * NN];          // 64MB
__device__ __half g_P0[(size_t)B_ * NN];          // 8MB
__device__ float  g_e [B_ * H_ * S_];

// ---------------- helpers ----------------
__device__ __forceinline__ uint32_t smem_u32(const void* p){
    uint32_t a;
    asm("{ .reg .u64 t; cvta.to.shared.u64 t, %1; cvt.u32.u64 %0, t; }" : "=r"(a) : "l"(p));
    return a;
}
__device__ __forceinline__ void ldsm_x4(uint32_t* r, uint32_t addr){
    asm volatile("ldmatrix.sync.aligned.m8n8.x4.shared.b16 {%0,%1,%2,%3}, [%4];"
                 : "=r"(r[0]),"=r"(r[1]),"=r"(r[2]),"=r"(r[3]) : "r"(addr));
}
__device__ __forceinline__ void ldsm_x4t(uint32_t* r, uint32_t addr){
    asm volatile("ldmatrix.sync.aligned.m8n8.x4.trans.shared.b16 {%0,%1,%2,%3}, [%4];"
                 : "=r"(r[0]),"=r"(r[1]),"=r"(r[2]),"=r"(r[3]) : "r"(addr));
}
__device__ __forceinline__ void mma16816(float* c, const uint32_t* a, const uint32_t* b){
    asm volatile("mma.sync.aligned.m16n8k16.row.col.f32.f16.f16.f32 "
                 "{%0,%1,%2,%3}, {%4,%5,%6,%7}, {%8,%9}, {%0,%1,%2,%3};"
                 : "+f"(c[0]),"+f"(c[1]),"+f"(c[2]),"+f"(c[3])
                 : "r"(a[0]),"r"(a[1]),"r"(a[2]),"r"(a[3]),"r"(b[0]),"r"(b[1]));
}
__device__ __forceinline__ void cp16(uint32_t dst, const void* src){
    asm volatile("cp.async.cg.shared.global [%0], [%1], 16;" :: "r"(dst), "l"(src) : "memory");
}
#define CP_COMMIT() asm volatile("cp.async.commit_group;" ::: "memory")
#define CP_WAIT(n)  asm volatile("cp.async.wait_group %0;" :: "n"(n) : "memory")
__device__ __forceinline__ float lrelu(float z){ return z > 0.f ? z : ALPHA_ * z; }

// ---------------------------------------------------------------------------
// FIRST:  P0[b, n](fp16) = inputs[b,0,:](fp16) @ Wf[h, 0:F, :]     (M=256)
// !FIRST: Wh = lrelu( A2 @ Wf[h, F:2F, :] + P0 );  e += Wh . att_w
// ---------------------------------------------------------------------------
template<bool FIRST>
__global__ void __launch_bounds__(512, 1)
gat_gemm(const float* __restrict__ att_w)
{
    extern __shared__ char smem[];
    const uint32_t sb = smem_u32(smem);
    const int tid   = threadIdx.x;
    const int lane  = tid & 31;
    const int wid   = tid >> 5;
    const int warpM = wid & 1;       // 2 M-warps (64 rows)
    const int warpN = wid >> 1;      // 8 N-warps (32 cols)

    const int mBase = blockIdx.x * 128;
    const int nTile = blockIdx.y;
    const int nBase = nTile * 256;
    const int h     = nTile >> 3;
    const int f0    = (nTile & 7) * 256;

    const size_t aStride = FIRST ? (size_t)(8*KK) : (size_t)KK;
    const __half* gB = g_Wf + ((size_t)h*(2*F_) + (FIRST ? 0 : F_)) * F_ + f0;

    float* sAw = (float*)(smem + AW_OFF);
    if (!FIRST && tid < 256) sAw[tid] = att_w[(size_t)h*F_ + f0 + tid];

    auto issue = [&](int s, int kB){
        // A: 128 rows x 8 chunks(16B) = 1024 chunks, 512 thr -> 2 each
        #pragma unroll
        for (int i = 0; i < 2; i++){
            const int idx = tid + (i << 9);
            const int row = idx >> 3, ch = idx & 7;
            cp16(sb + A_OFF(s) + row*A_PITCH + ch*16,
                 g_A2 + (size_t)(mBase + row)*aStride + kB + ch*8);
        }
        // B: 64 rows x 32 chunks = 2048 chunks -> 4 each
        #pragma unroll
        for (int i = 0; i < 4; i++){
            const int idx = tid + (i << 9);
            const int row = idx >> 5, ch = idx & 31;
            cp16(sb + B_OFF(s) + row*B_PITCH + ch*16,
                 gB + (size_t)(kB + row)*F_ + ch*8);
        }
    };

    // per-warp fragment addressing
    const uint32_t aRow = (uint32_t)(warpM*64 + (lane & 15)) * A_PITCH + (((uint32_t)lane >> 4) << 4);
    const uint32_t bRow = (uint32_t)(lane & 15) * B_PITCH
                        + (uint32_t)(warpN*32 + ((lane >> 4) << 3)) * 2;

    uint32_t af[2][4][4], bf[2][2][4];

    auto load_a = [&](int buf, uint32_t aB, int kk16){
        #pragma unroll
        for (int mf = 0; mf < 4; mf++)
            ldsm_x4(af[buf][mf], aB + aRow + (uint32_t)(mf*16)*A_PITCH + (uint32_t)(kk16*16)*2);
    };
    auto load_b = [&](int buf, uint32_t bB, int kk16){
        #pragma unroll
        for (int nq = 0; nq < 2; nq++)
            ldsm_x4t(bf[buf][nq], bB + (uint32_t)(kk16*16)*B_PITCH + bRow + (uint32_t)(nq*16)*2);
    };

    float acc[4][4][4];
    #pragma unroll
    for (int a = 0; a < 4; a++)
        #pragma unroll
        for (int b = 0; b < 4; b++)
            #pragma unroll
            for (int c = 0; c < 4; c++) acc[a][b][c] = 0.f;

    // ---- prologue: 3 stages in flight ----
    issue(0, 0);   CP_COMMIT();
    issue(1, 64);  CP_COMMIT();
    issue(2, 128); CP_COMMIT();
    CP_WAIT(2);
    __syncthreads();
    load_a(0, sb + A_OFF(0), 0);
    load_b(0, sb + B_OFF(0), 0);

    for (int kt = 0; kt < NKT; kt++){
        const int s  = kt & 3;
        const int sn = (kt + 1) & 3;
        const uint32_t aB  = sb + A_OFF(s),  bB  = sb + B_OFF(s);
        const uint32_t aBn = sb + A_OFF(sn), bBn = sb + B_OFF(sn);

        #pragma unroll
        for (int kk = 0; kk < 4; kk++){
            const int cur = kk & 1, nxt = cur ^ 1;
            if (kk == 0 && kt + 3 < NKT){
                issue((kt + 3) & 3, (kt + 3) * 64);
                CP_COMMIT();
            }
            if (kk < 3){
                load_a(nxt, aB, kk + 1);
                load_b(nxt, bB, kk + 1);
            } else if (kt + 1 < NKT){
                CP_WAIT(2);
                __syncthreads();
                load_a(nxt, aBn, 0);
                load_b(nxt, bBn, 0);
            }
            #pragma unroll
            for (int mf = 0; mf < 4; mf++)
                #pragma unroll
                for (int nq = 0; nq < 2; nq++){
                    mma16816(acc[mf][2*nq],   af[cur][mf], &bf[cur][nq][0]);
                    mma16816(acc[mf][2*nq+1], af[cur][mf], &bf[cur][nq][2]);
                }
        }
    }

    // ---------------- epilogue ----------------
    const int g  = lane >> 2;
    const int tg = lane & 3;

    #pragma unroll
    for (int mf = 0; mf < 4; mf++){
        const int r0 = mBase + warpM*64 + mf*16 + g;
        const int r1 = r0 + 8;
        if (FIRST){
            #pragma unroll
            for (int nf = 0; nf < 4; nf++){
                const int c0 = nBase + warpN*32 + nf*8 + tg*2;
                *reinterpret_cast<__half2*>(&g_P0[(size_t)r0*NN + c0]) = __floats2half2_rn(acc[mf][nf][0], acc[mf][nf][1]);
                *reinterpret_cast<__half2*>(&g_P0[(size_t)r1*NN + c0]) = __floats2half2_rn(acc[mf][nf][2], acc[mf][nf][3]);
            }
        } else {
            float e0 = 0.f, e1 = 0.f;
            #pragma unroll
            for (int nf = 0; nf < 4; nf++){
                const int lc = warpN*32 + nf*8 + tg*2;
                const int c0 = nBase + lc;
                const float2 p0 = __half22float2(*reinterpret_cast<const __half2*>(&g_P0[(size_t)(r0 >> 3)*NN + c0]));
                const float2 p1 = __half22float2(*reinterpret_cast<const __half2*>(&g_P0[(size_t)(r1 >> 3)*NN + c0]));
                const float v00 = lrelu(acc[mf][nf][0] + p0.x);
                const float v01 = lrelu(acc[mf][nf][1] + p0.y);
                const float v10 = lrelu(acc[mf][nf][2] + p1.x);
                const float v11 = lrelu(acc[mf][nf][3] + p1.y);
                e0 += v00*sAw[lc] + v01*sAw[lc+1];
                e1 += v10*sAw[lc] + v11*sAw[lc+1];
                *reinterpret_cast<__half2*>(&g_Wh[(size_t)r0*NN + c0]) = __floats2half2_rn(v00, v01);
                *reinterpret_cast<__half2*>(&g_Wh[(size_t)r1*NN + c0]) = __floats2half2_rn(v10, v11);
            }
            e0 += __shfl_xor_sync(0xffffffffu, e0, 1);
            e0 += __shfl_xor_sync(0xffffffffu, e0, 2);
            e1 += __shfl_xor_sync(0xffffffffu, e1, 1);
            e1 += __shfl_xor_sync(0xffffffffu, e1, 2);
            if (tg == 0){
                atomicAdd(&g_e[(r0 >> 3)*64 + h*8 + (r0 & 7)], e0);
                atomicAdd(&g_e[(r1 >> 3)*64 + h*8 + (r1 & 7)], e1);
            }
        }
    }
}

// ---------------------------------------------------------------------------
__global__ void zero_e_kernel(){
    int i = blockIdx.x * blockDim.x + threadIdx.x;
    if (i < B_*H_*S_) g_e[i] = 0.f;
}

// inputs fp32 -> g_A2 fp16
__global__ void __launch_bounds__(256) conv_in(const float* __restrict__ in){
    size_t i = (size_t)blockIdx.x * 256 + threadIdx.x;
    const float2 v = ((const float2*)in)[i];
    ((__half2*)g_A2)[i] = __floats2half2_rn(v.x, v.y);
}

// W fp32 -> g_Wf fp16 (same layout)
__global__ void __launch_bounds__(256) conv_W(const float* __restrict__ W){
    size_t i = (size_t)blockIdx.x * 256 + threadIdx.x;
    const float4 v = ((const float4*)W)[i];
    __half2 lo = __floats2half2_rn(v.x, v.y);
    __half2 hi = __floats2half2_rn(v.z, v.w);
    uint2 pk;
    pk.x = *reinterpret_cast<uint32_t*>(&lo);
    pk.y = *reinterpret_cast<uint32_t*>(&hi);
    ((uint2*)g_Wf)[i] = pk;
}

// out[b,s,f] = inputs + mean_h(bias) + sum_h attn/H * Wh
__global__ void __launch_bounds__(256) gat_out(const float* __restrict__ in,
                                               const float* __restrict__ bias,
                                               float* __restrict__ out){
    const int bs = blockIdx.x;
    const int b = bs >> 3, s = bs & 7;
    __shared__ float sAttn[H_];
    const int tid = threadIdx.x;
    if (tid < H_){
        float ev[S_]; float mx = -1e30f;
        #pragma unroll
        for (int s2 = 0; s2 < S_; s2++){ ev[s2] = g_e[b*64 + tid*8 + s2]; mx = fmaxf(mx, ev[s2]); }
        float sum = 0.f;
        #pragma unroll
        for (int s2 = 0; s2 < S_; s2++) sum += __expf(ev[s2] - mx);
        sAttn[tid] = __expf(ev[s] - mx) * 0.125f / sum;
    }
    __syncthreads();
    const float2*  in2 = (const float2*)(in + (size_t)bs * F_);
    const float2*  bi2 = (const float2*)bias;
    const __half2* w2  = (const __half2*)(g_Wh + (size_t)bs * NN);
    float2* o2 = (float2*)(out + (size_t)bs * F_);
    #pragma unroll
    for (int i = tid; i < F_/2; i += 256){
        float2 a = in2[i];
        #pragma unroll
        for (int hh = 0; hh < H_; hh++){
            const float2 w  = __half22float2(w2[hh*(F_/2) + i]);
            const float2 bb = bi2[hh*(F_/2) + i];
            a.x += sAttn[hh]*w.x + 0.125f*bb.x;
            a.y += sAttn[hh]*w.y + 0.125f*bb.y;
        }
        o2[i] = a;
    }
}

// ---------------------------------------------------------------------------
extern "C" void kernel_launch(void* const* d_in, const int* in_sizes, int n_in,
                              void* d_out, int out_size)
{
    const float* inputs = (const float*)d_in[0];
    const float* W      = (const float*)d_in[1];
    const float* att_w  = (const float*)d_in[2];
    const float* bias   = (const float*)d_in[3];
    float* out = (float*)d_out;

    cudaFuncSetAttribute(gat_gemm<true>,  cudaFuncAttributeMaxDynamicSharedMemorySize, SMEM_TOTAL);
    cudaFuncSetAttribute(gat_gemm<false>, cudaFuncAttributeMaxDynamicSharedMemorySize, SMEM_TOTAL);

    zero_e_kernel<<<(B_*H_*S_ + 255)/256, 256>>>();
    conv_in<<<(M2*KK/2)/256, 256>>>(inputs);
    conv_W<<<(H_*2*F_*F_/4)/256, 256>>>(W);

    gat_gemm<true ><<<dim3(2, 64),  512, SMEM_TOTAL>>>(att_w);
    gat_gemm<false><<<dim3(16, 64), 512, SMEM_TOTAL>>>(att_w);

    gat_out<<<M2, 256>>>(inputs, bias, out);
}

// round 7
// speedup vs baseline: 1.3501x; 1.0132x over previous
#include <cuda_runtime.h>
#include <cuda_fp16.h>
#include <cstdint>

// ---------------- problem dims ----------------
#define B_  256
#define S_  8
#define F_  2048
#define H_  8
#define NN  (H_*F_)     // 16384
#define M2  (B_*S_)     // 2048
#define KK  2048        // K per split GEMM
#define ALPHA_ 0.3f

// ---------------- GEMM tiling ----------------
// CTA tile 128(M) x 128(N), BK=64, 3-stage cp.async, 256 threads,
// warp grid 2(M) x 4(N) -> warp tile 64x32.  2 CTAs/SM.
#define NKT 32                      // 2048/64

// smem byte layout (per stage: A | B)
#define A_PITCH 144                 // 64 halves + 8 pad (16B row phase step -> conflict-free)
#define B_PITCH 272                 // 128 halves + 8 pad (16B row phase step)
#define A_ST (128*A_PITCH)          // 18432
#define B_ST (64*B_PITCH)           // 17408
#define STAGE_ST (A_ST + B_ST)      // 35840
#define A_OFF(s) ((s)*STAGE_ST)
#define B_OFF(s) ((s)*STAGE_ST + A_ST)
#define AW_OFF   (3*STAGE_ST)       // 107520
#define SMEM_TOTAL (AW_OFF + 128*4) // 108032  (x2 CTAs = 216KB < 227KB)

// ---------------- device scratch ----------------
__device__ __half g_A2[(size_t)M2 * KK];          // 8MB
__device__ __half g_Wf[(size_t)H_ * 2 * F_ * F_]; // 134MB
__device__ __half g_Wh[(size_t)M2 * NN];          // 64MB
__device__ __half g_P0[(size_t)B_ * NN];          // 8MB
__device__ float  g_e [B_ * H_ * S_];

// ---------------- helpers ----------------
__device__ __forceinline__ uint32_t smem_u32(const void* p){
    uint32_t a;
    asm("{ .reg .u64 t; cvta.to.shared.u64 t, %1; cvt.u32.u64 %0, t; }" : "=r"(a) : "l"(p));
    return a;
}
__device__ __forceinline__ void ldsm_x4(uint32_t* r, uint32_t addr){
    asm volatile("ldmatrix.sync.aligned.m8n8.x4.shared.b16 {%0,%1,%2,%3}, [%4];"
                 : "=r"(r[0]),"=r"(r[1]),"=r"(r[2]),"=r"(r[3]) : "r"(addr));
}
__device__ __forceinline__ void ldsm_x4t(uint32_t* r, uint32_t addr){
    asm volatile("ldmatrix.sync.aligned.m8n8.x4.trans.shared.b16 {%0,%1,%2,%3}, [%4];"
                 : "=r"(r[0]),"=r"(r[1]),"=r"(r[2]),"=r"(r[3]) : "r"(addr));
}
__device__ __forceinline__ void mma16816(float* c, const uint32_t* a, const uint32_t* b){
    asm volatile("mma.sync.aligned.m16n8k16.row.col.f32.f16.f16.f32 "
                 "{%0,%1,%2,%3}, {%4,%5,%6,%7}, {%8,%9}, {%0,%1,%2,%3};"
                 : "+f"(c[0]),"+f"(c[1]),"+f"(c[2]),"+f"(c[3])
                 : "r"(a[0]),"r"(a[1]),"r"(a[2]),"r"(a[3]),"r"(b[0]),"r"(b[1]));
}
__device__ __forceinline__ void cp16(uint32_t dst, const void* src){
    asm volatile("cp.async.cg.shared.global [%0], [%1], 16;" :: "r"(dst), "l"(src) : "memory");
}
#define CP_COMMIT() asm volatile("cp.async.commit_group;" ::: "memory")
#define CP_WAIT(n)  asm volatile("cp.async.wait_group %0;" :: "n"(n) : "memory")
__device__ __forceinline__ float lrelu(float z){ return z > 0.f ? z : ALPHA_ * z; }

// ---------------------------------------------------------------------------
// FIRST:  P0[b, n](fp16) = inputs[b,0,:](fp16) @ Wf[h, 0:F, :]     (M=256)
// !FIRST: Wh = lrelu( A2 @ Wf[h, F:2F, :] + P0 );  e += Wh . att_w
// ---------------------------------------------------------------------------
template<bool FIRST>
__global__ void __launch_bounds__(256, 2)
gat_gemm(const float* __restrict__ att_w)
{
    extern __shared__ char smem[];
    const uint32_t sb = smem_u32(smem);
    const int tid   = threadIdx.x;
    const int lane  = tid & 31;
    const int wid   = tid >> 5;
    const int warpM = wid & 1;       // 2 M-warps (64 rows)
    const int warpN = wid >> 1;      // 4 N-warps (32 cols)

    const int mBase = blockIdx.x * 128;
    const int nTile = blockIdx.y;
    const int nBase = nTile * 128;
    const int h     = nTile >> 4;          // 16 N-tiles of 128 per head
    const int f0    = (nTile & 15) * 128;

    const size_t aStride = FIRST ? (size_t)(8*KK) : (size_t)KK;
    const __half* gB = g_Wf + ((size_t)h*(2*F_) + (FIRST ? 0 : F_)) * F_ + f0;

    float* sAw = (float*)(smem + AW_OFF);
    if (!FIRST && tid < 128) sAw[tid] = att_w[(size_t)h*F_ + f0 + tid];

    // incremental cp.async addressing (one base pointer per matrix)
    const __half* aSrc = g_A2 + (size_t)(mBase + (tid >> 3))*aStride + (tid & 7)*8;
    const __half* bSrc = gB   + (size_t)(tid >> 4)*F_ + (tid & 15)*8;
    const uint32_t aDst = sb + (uint32_t)(tid >> 3)*A_PITCH + (uint32_t)(tid & 7)*16;
    const uint32_t bDst = sb + A_ST + (uint32_t)(tid >> 4)*B_PITCH + (uint32_t)(tid & 15)*16;

    auto issue = [&](int s, int kt){
        const __half* a = aSrc + (size_t)kt * 64;        // advance 64 K-cols
        const __half* b = bSrc + (size_t)kt * 64 * F_;   // advance 64 K-rows
        const uint32_t ad = aDst + (uint32_t)s*STAGE_ST;
        const uint32_t bd = bDst + (uint32_t)s*STAGE_ST;
        #pragma unroll
        for (int i = 0; i < 4; i++)                      // A: 128 rows x 8 chunks
            cp16(ad + (uint32_t)(i*32*A_PITCH), a + (size_t)(i*32)*aStride);
        #pragma unroll
        for (int i = 0; i < 4; i++)                      // B: 64 rows x 16 chunks
            cp16(bd + (uint32_t)(i*16*B_PITCH), b + (size_t)(i*16)*F_);
        CP_COMMIT();
    };

    // fragment addressing
    const uint32_t aRow = (uint32_t)(warpM*64 + (lane & 15))*A_PITCH + (((uint32_t)lane >> 4) << 4);
    const uint32_t bRow = (uint32_t)(lane & 15)*B_PITCH
                        + (uint32_t)(warpN*32 + ((lane >> 4) << 3))*2;

    uint32_t af[2][4][4], bfv[2][4];

    auto load_a = [&](int buf, uint32_t aB, int kk16){
        #pragma unroll
        for (int mf = 0; mf < 4; mf++)
            ldsm_x4(af[buf][mf], aB + aRow + (uint32_t)(mf*16)*A_PITCH + (uint32_t)kk16*32);
    };
    auto load_b = [&](uint32_t bB, int kk16){
        #pragma unroll
        for (int nq = 0; nq < 2; nq++)
            ldsm_x4t(bfv[nq], bB + (uint32_t)(kk16*16)*B_PITCH + bRow + (uint32_t)(nq*16)*2);
    };

    float acc[4][4][4];
    #pragma unroll
    for (int a = 0; a < 4; a++)
        #pragma unroll
        for (int b = 0; b < 4; b++)
            #pragma unroll
            for (int c = 0; c < 4; c++) acc[a][b][c] = 0.f;

    // ---- prologue: 2 stages in flight ----
    issue(0, 0);
    issue(1, 1);
    CP_WAIT(1);
    __syncthreads();
    load_a(0, sb + A_OFF(0), 0);

    for (int kt = 0; kt < NKT; kt++){
        const int s  = kt % 3;
        const int sn = (kt + 1) % 3;
        const uint32_t aB = sb + A_OFF(s);
        const uint32_t bB = sb + B_OFF(s);

        #pragma unroll
        for (int kk = 0; kk < 4; kk++){
            const int cur = kk & 1, nxt = cur ^ 1;
            if (kk == 0 && kt + 2 < NKT)
                issue((kt + 2) % 3, kt + 2);
            load_b(bB, kk);                 // B frag for this kk (single-buffered)
            if (kk < 3){
                load_a(nxt, aB, kk + 1);
            } else if (kt + 1 < NKT){
                CP_WAIT(1);
                __syncthreads();
                load_a(nxt, sb + A_OFF(sn), 0);
            }
            #pragma unroll
            for (int mf = 0; mf < 4; mf++)
                #pragma unroll
                for (int nq = 0; nq < 2; nq++){
                    mma16816(acc[mf][2*nq],   af[cur][mf], &bfv[nq][0]);
                    mma16816(acc[mf][2*nq+1], af[cur][mf], &bfv[nq][2]);
                }
        }
    }

    // ---------------- epilogue ----------------
    const int g  = lane >> 2;
    const int tg = lane & 3;

    #pragma unroll
    for (int mf = 0; mf < 4; mf++){
        const int r0 = mBase + warpM*64 + mf*16 + g;
        const int r1 = r0 + 8;
        if (FIRST){
            #pragma unroll
            for (int nf = 0; nf < 4; nf++){
                const int c0 = nBase + warpN*32 + nf*8 + tg*2;
                *reinterpret_cast<__half2*>(&g_P0[(size_t)r0*NN + c0]) = __floats2half2_rn(acc[mf][nf][0], acc[mf][nf][1]);
                *reinterpret_cast<__half2*>(&g_P0[(size_t)r1*NN + c0]) = __floats2half2_rn(acc[mf][nf][2], acc[mf][nf][3]);
            }
        } else {
            float e0 = 0.f, e1 = 0.f;
            #pragma unroll
            for (int nf = 0; nf < 4; nf++){
                const int lc = warpN*32 + nf*8 + tg*2;
                const int c0 = nBase + lc;
                const float2 p0 = __half22float2(*reinterpret_cast<const __half2*>(&g_P0[(size_t)(r0 >> 3)*NN + c0]));
                const float2 p1 = __half22float2(*reinterpret_cast<const __half2*>(&g_P0[(size_t)(r1 >> 3)*NN + c0]));
                const float v00 = lrelu(acc[mf][nf][0] + p0.x);
                const float v01 = lrelu(acc[mf][nf][1] + p0.y);
                const float v10 = lrelu(acc[mf][nf][2] + p1.x);
                const float v11 = lrelu(acc[mf][nf][3] + p1.y);
                e0 += v00*sAw[lc] + v01*sAw[lc+1];
                e1 += v10*sAw[lc] + v11*sAw[lc+1];
                *reinterpret_cast<__half2*>(&g_Wh[(size_t)r0*NN + c0]) = __floats2half2_rn(v00, v01);
                *reinterpret_cast<__half2*>(&g_Wh[(size_t)r1*NN + c0]) = __floats2half2_rn(v10, v11);
            }
            e0 += __shfl_xor_sync(0xffffffffu, e0, 1);
            e0 += __shfl_xor_sync(0xffffffffu, e0, 2);
            e1 += __shfl_xor_sync(0xffffffffu, e1, 1);
            e1 += __shfl_xor_sync(0xffffffffu, e1, 2);
            if (tg == 0){
                atomicAdd(&g_e[(r0 >> 3)*64 + h*8 + (r0 & 7)], e0);
                atomicAdd(&g_e[(r1 >> 3)*64 + h*8 + (r1 & 7)], e1);
            }
        }
    }
}

// ---------------------------------------------------------------------------
__global__ void zero_e_kernel(){
    int i = blockIdx.x * blockDim.x + threadIdx.x;
    if (i < B_*H_*S_) g_e[i] = 0.f;
}

// inputs fp32 -> g_A2 fp16
__global__ void __launch_bounds__(256) conv_in(const float* __restrict__ in){
    size_t i = (size_t)blockIdx.x * 256 + threadIdx.x;
    const float2 v = ((const float2*)in)[i];
    ((__half2*)g_A2)[i] = __floats2half2_rn(v.x, v.y);
}

// W fp32 -> g_Wf fp16 (same layout)
__global__ void __launch_bounds__(256) conv_W(const float* __restrict__ W){
    size_t i = (size_t)blockIdx.x * 256 + threadIdx.x;
    const float4 v = ((const float4*)W)[i];
    __half2 lo = __floats2half2_rn(v.x, v.y);
    __half2 hi = __floats2half2_rn(v.z, v.w);
    uint2 pk;
    pk.x = *reinterpret_cast<uint32_t*>(&lo);
    pk.y = *reinterpret_cast<uint32_t*>(&hi);
    ((uint2*)g_Wf)[i] = pk;
}

// out[b,s,f] = inputs + mean_h(bias) + sum_h attn/H * Wh
__global__ void __launch_bounds__(256) gat_out(const float* __restrict__ in,
                                               const float* __restrict__ bias,
                                               float* __restrict__ out){
    const int bs = blockIdx.x;
    const int b = bs >> 3, s = bs & 7;
    __shared__ float sAttn[H_];
    const int tid = threadIdx.x;
    if (tid < H_){
        float ev[S_]; float mx = -1e30f;
        #pragma unroll
        for (int s2 = 0; s2 < S_; s2++){ ev[s2] = g_e[b*64 + tid*8 + s2]; mx = fmaxf(mx, ev[s2]); }
        float sum = 0.f;
        #pragma unroll
        for (int s2 = 0; s2 < S_; s2++) sum += __expf(ev[s2] - mx);
        sAttn[tid] = __expf(ev[s] - mx) * 0.125f / sum;
    }
    __syncthreads();
    const float2*  in2 = (const float2*)(in + (size_t)bs * F_);
    const float2*  bi2 = (const float2*)bias;
    const __half2* w2  = (const __half2*)(g_Wh + (size_t)bs * NN);
    float2* o2 = (float2*)(out + (size_t)bs * F_);
    #pragma unroll
    for (int i = tid; i < F_/2; i += 256){
        float2 a = in2[i];
        #pragma unroll
        for (int hh = 0; hh < H_; hh++){
            const float2 w  = __half22float2(w2[hh*(F_/2) + i]);
            const float2 bb = bi2[hh*(F_/2) + i];
            a.x += sAttn[hh]*w.x + 0.125f*bb.x;
            a.y += sAttn[hh]*w.y + 0.125f*bb.y;
        }
        o2[i] = a;
    }
}

// ---------------------------------------------------------------------------
extern "C" void kernel_launch(void* const* d_in, const int* in_sizes, int n_in,
                              void* d_out, int out_size)
{
    const float* inputs = (const float*)d_in[0];
    const float* W      = (const float*)d_in[1];
    const float* att_w  = (const float*)d_in[2];
    const float* bias   = (const float*)d_in[3];
    float* out = (float*)d_out;

    cudaFuncSetAttribute(gat_gemm<true>,  cudaFuncAttributeMaxDynamicSharedMemorySize, SMEM_TOTAL);
    cudaFuncSetAttribute(gat_gemm<false>, cudaFuncAttributeMaxDynamicSharedMemorySize, SMEM_TOTAL);

    zero_e_kernel<<<(B_*H_*S_ + 255)/256, 256>>>();
    conv_in<<<(M2*KK/2)/256, 256>>>(inputs);
    conv_W<<<(H_*2*F_*F_/4)/256, 256>>>(W);

    gat_gemm<true ><<<dim3(2, 128),  256, SMEM_TOTAL>>>(att_w);
    gat_gemm<false><<<dim3(16, 128), 256, SMEM_TOTAL>>>(att_w);

    gat_out<<<M2, 256>>>(inputs, bias, out);
}